// round 6
// baseline (speedup 1.0000x reference)
#include <cuda_runtime.h>
#include <cuda_fp16.h>
#include <cstdint>

// ---------------------------------------------------------------------------
// ConvCapsuleLayer3D, fully fused conv+routing:
//   pad_kernel   : x -> g_xpad2 half2(ch even, ch odd) padded volume
//                  [nb(8)][ch2(8)][34][34][34]
//   wfrag_kernel : W -> m16n8k16 A-fragments, K permuted by channel pairing
//   fused_kernel : per CTA: 4 IC-GEMMs (256oc x 32pos, K=432, A shared
//                  across ICs) -> votes in smem -> 3-iter sigmoid routing
//                  -> squash -> coalesced output. No votes gmem round-trip.
// ---------------------------------------------------------------------------

#define KTOT 432
#define NQ   216
#define PADC 39304     // 34^3
#define PADZ 1156
#define PADY 34

// fused halo strides (half2 units): [ic][ch2(8)][zp(3)][yp(3)][xp(34)]
#define HF_KD   102
#define HF_CI   306    // 3*34*3
#define HALO_IC 2448   // 8*306
#define HALO_W  9792   // 4*2448

// smem word offsets (uint32 units)
#define OFF_TBL   0        // 224 ints
#define OFF_HALO  224      // 9792
#define OFF_VOTES 10016    // fp16 votes [ic(4)][pos(32)][oc(256)] = 16384 words
#define OFF_ACT   26400    // fp32 act  [row(256)][33] = 8448 words
#define SMEM_WORDS 34848
#define SMEM_BYTES (SMEM_WORDS * 4)   // 139392

__device__ uint32_t g_xpad2[8 * 8 * PADC];   // 10 MB half2 pairs
__device__ uint4    g_wfrag16[27 * 16 * 32]; // 221 KB A fragments

// ---------------------------------------------------------------------------
__global__ void pad_kernel(const float* __restrict__ X) {
    int idx = blockIdx.x * 256 + threadIdx.x;
    if (idx >= 8 * 8 * PADC) return;
    int nb = idx / (8 * PADC);
    int r  = idx - nb * (8 * PADC);
    int ch2 = r / PADC;
    int pp  = r - ch2 * PADC;
    int zp = pp / PADZ;  pp -= zp * PADZ;
    int yp = pp / PADY;
    int xp = pp - yp * PADY;
    int z = zp - 1, y = yp - 1, x = xp - 1;
    float v0 = 0.f, v1 = 0.f;
    if ((unsigned)z < 32u && (unsigned)y < 32u && (unsigned)x < 32u) {
        int pos = (z << 10) + (y << 5) + x;
        const float* src = X + ((size_t)(nb * 16 + ch2 * 2) << 15) + pos;
        v0 = src[0];
        v1 = src[32768];
    }
    __half2 h = __floats2half2_rn(v0, v1);
    g_xpad2[idx] = *(uint32_t*)&h;
}

// A fragments: i = ks*512 + m16*32 + lane, pair q=(cihalf, tap)
__global__ void wfrag_kernel(const float* __restrict__ W) {
    int i = blockIdx.x * 256 + threadIdx.x;
    if (i >= 27 * 16 * 32) return;
    int lane = i & 31;
    int m16  = (i >> 5) & 15;
    int ks   = i >> 9;
    int gid = lane >> 2, tig = lane & 3;
    uint32_t v[4];
    #pragma unroll
    for (int j = 0; j < 4; ++j) {
        int m = m16 * 16 + gid + ((j & 1) ? 8 : 0);
        int q = ks * 8 + tig + ((j >= 2) ? 4 : 0);
        int cihalf = q / 27;
        int tap    = q - cihalf * 27;
        int k0 = (2 * cihalf) * 27 + tap;
        __half2 h = __floats2half2_rn(W[m * KTOT + k0], W[m * KTOT + k0 + 27]);
        v[j] = *(uint32_t*)&h;
    }
    g_wfrag16[i] = make_uint4(v[0], v[1], v[2], v[3]);
}

// ---------------------------------------------------------------------------
// fused kernel: grid (1024 [z,y], 2 [b]), 512 threads
// GEMM: 16 warps = wm(4) x wn(4); warp = 64oc x 8pos, 4 IC accumulators
// ---------------------------------------------------------------------------
__global__ void __launch_bounds__(512, 1)
fused_kernel(const float* __restrict__ bias, float* __restrict__ out) {
    extern __shared__ uint32_t sm[];
    int*      tbl    = (int*)(sm + OFF_TBL);
    uint32_t* halo   = sm + OFF_HALO;
    __half*   votes  = (__half*)(sm + OFF_VOTES);
    float*    s_act  = (float*)(sm + OFF_ACT);

    const int tid  = threadIdx.x;
    const int w    = tid >> 5, lane = tid & 31;
    const int gid  = lane >> 2, tig = lane & 3;
    const int wm   = w >> 2;            // 0..3
    const int wn   = w & 3;             // 0..3

    const int bx = blockIdx.x;          // 0..1023
    const int b  = blockIdx.y;          // 0..1
    const int z  = bx >> 5, y = bx & 31;
    const int p0 = (z << 10) + (y << 5);

    // pair -> halo offset table
    for (int q = tid; q < NQ; q += 512) {
        int cihalf = q / 27;
        int tap    = q - cihalf * 27;
        int kd = tap / 9;  int rr = tap - kd * 9;
        int kh = rr / 3;   int kw = rr - kh * 3;
        tbl[q] = cihalf * HF_CI + kd * HF_KD + kh * 34 + kw;
    }
    // halo: [ic][ch2][zp 3][yp 3][xp 34]
    {
        const uint32_t* xbase = g_xpad2 + (size_t)(b * 4) * (8 * PADC)
                              + z * PADZ + y * PADY;
        for (int i = tid; i < HALO_W; i += 512) {
            int ic  = i / HALO_IC;
            int r   = i - ic * HALO_IC;
            int ch2 = r / HF_CI;
            int rr  = r - ch2 * HF_CI;
            int zp  = rr / HF_KD;
            int r2  = rr - zp * HF_KD;
            int yp  = r2 / 34;
            int xp  = r2 - yp * 34;
            halo[i] = xbase[(size_t)(ic * 8 + ch2) * PADC
                            + zp * PADZ + yp * PADY + xp];
        }
    }
    __syncthreads();

    // ---------------- GEMM phase ----------------
    const int ncol = wn * 8 + gid;     // x position 0..31 (B n-index)

    float acc[4][4][4];
    #pragma unroll
    for (int ic = 0; ic < 4; ++ic)
        #pragma unroll
        for (int mi = 0; mi < 4; ++mi)
            #pragma unroll
            for (int c = 0; c < 4; ++c) acc[ic][mi][c] = 0.f;

    const uint4* wf = g_wfrag16 + (size_t)(wm * 4) * 32 + lane;

    #pragma unroll 3
    for (int ks = 0; ks < 27; ++ks) {
        const int q0 = tbl[ks * 8 + tig] + ncol;
        const int q1 = tbl[ks * 8 + tig + 4] + ncol;
        uint4 A[4];
        #pragma unroll
        for (int mi = 0; mi < 4; ++mi)
            A[mi] = wf[(ks * 16 + mi) * 32];
        #pragma unroll
        for (int ic = 0; ic < 4; ++ic) {
            uint32_t b0 = halo[ic * HALO_IC + q0];
            uint32_t b1 = halo[ic * HALO_IC + q1];
            #pragma unroll
            for (int mi = 0; mi < 4; ++mi) {
                asm volatile(
                    "mma.sync.aligned.m16n8k16.row.col.f32.f16.f16.f32 "
                    "{%0,%1,%2,%3}, {%4,%5,%6,%7}, {%8,%9}, {%0,%1,%2,%3};"
                    : "+f"(acc[ic][mi][0]), "+f"(acc[ic][mi][1]),
                      "+f"(acc[ic][mi][2]), "+f"(acc[ic][mi][3])
                    : "r"(A[mi].x), "r"(A[mi].y), "r"(A[mi].z), "r"(A[mi].w),
                      "r"(b0), "r"(b1));
            }
        }
    }
    __syncthreads();   // halo no longer needed; votes region may alias nothing

    // votes -> smem: votes[ic][pos][oc] fp16
    #pragma unroll
    for (int ic = 0; ic < 4; ++ic)
        #pragma unroll
        for (int mi = 0; mi < 4; ++mi) {
            const int oc  = wm * 64 + mi * 16 + gid;
            const int pos = wn * 8 + tig * 2;
            __half* dst = votes + ((ic * 32 + pos) << 8) + oc;
            dst[0]       = __float2half_rn(acc[ic][mi][0]);
            dst[8]       = __float2half_rn(acc[ic][mi][2]);
            dst[256]     = __float2half_rn(acc[ic][mi][1]);
            dst[256 + 8] = __float2half_rn(acc[ic][mi][3]);
        }
    __syncthreads();

    // ---------------- routing phase ----------------
    // warp handles 2 positions; lane = (nc = lane>>2, q = lane&3), 8 atoms
    const int nc = lane >> 2, qq = lane & 3;
    float bb[8];
    {
        float4 a = *(const float4*)(bias + nc * 32 + qq * 8);
        float4 c = *(const float4*)(bias + nc * 32 + qq * 8 + 4);
        bb[0] = a.x; bb[1] = a.y; bb[2] = a.z; bb[3] = a.w;
        bb[4] = c.x; bb[5] = c.y; bb[6] = c.z; bb[7] = c.w;
    }

    #pragma unroll
    for (int pp = 0; pp < 2; ++pp) {
        const int posl = w * 2 + pp;
        float v[4][8];
        #pragma unroll
        for (int ic = 0; ic < 4; ++ic) {
            uint4 raw = *(const uint4*)(votes + ((ic * 32 + posl) << 8)
                                        + nc * 32 + qq * 8);
            float2 f;
            f = __half22float2(*(__half2*)&raw.x); v[ic][0] = f.x; v[ic][1] = f.y;
            f = __half22float2(*(__half2*)&raw.y); v[ic][2] = f.x; v[ic][3] = f.y;
            f = __half22float2(*(__half2*)&raw.z); v[ic][4] = f.x; v[ic][5] = f.y;
            f = __half22float2(*(__half2*)&raw.w); v[ic][6] = f.x; v[ic][7] = f.y;
        }

        float lgt[4] = {1.f, 1.f, 1.f, 1.f};
        float act[8];
        #pragma unroll
        for (int it = 0; it < 3; ++it) {
            float r[4];
            #pragma unroll
            for (int ic = 0; ic < 4; ++ic)
                r[ic] = 1.0f / (1.0f + __expf(-lgt[ic]));

            float pre[8], sql = 0.f;
            #pragma unroll
            for (int j = 0; j < 8; ++j) {
                float pv = bb[j];
                #pragma unroll
                for (int ic = 0; ic < 4; ++ic) pv = fmaf(r[ic], v[ic][j], pv);
                pre[j] = pv;
                sql = fmaf(pv, pv, sql);
            }
            sql += __shfl_xor_sync(0xFFFFFFFFu, sql, 1);
            sql += __shfl_xor_sync(0xFFFFFFFFu, sql, 2);
            float scale = sql / ((1.0f + sql) * sqrtf(sql + 1e-9f));
            #pragma unroll
            for (int j = 0; j < 8; ++j) act[j] = pre[j] * scale;

            if (it < 2) {
                #pragma unroll
                for (int ic = 0; ic < 4; ++ic) {
                    float d = 0.f;
                    #pragma unroll
                    for (int j = 0; j < 8; ++j) d = fmaf(v[ic][j], act[j], d);
                    d += __shfl_xor_sync(0xFFFFFFFFu, d, 1);
                    d += __shfl_xor_sync(0xFFFFFFFFu, d, 2);
                    lgt[ic] += d;
                }
            }
        }

        #pragma unroll
        for (int j = 0; j < 8; ++j)
            s_act[(nc * 32 + qq * 8 + j) * 33 + posl] = act[j];
    }
    __syncthreads();

    // ---------------- output: coalesced STG.128 ----------------
    {
        const int r = tid >> 1, h = tid & 1;
        const float* src = s_act + r * 33 + h * 16;
        float* dst = out + (((size_t)(b * 256 + r)) << 15) + p0 + h * 16;
        #pragma unroll
        for (int k = 0; k < 4; ++k) {
            float4 o;
            o.x = src[k * 4 + 0];
            o.y = src[k * 4 + 1];
            o.z = src[k * 4 + 2];
            o.w = src[k * 4 + 3];
            *(float4*)(dst + k * 4) = o;
        }
    }
}

// ---------------------------------------------------------------------------
extern "C" void kernel_launch(void* const* d_in, const int* in_sizes, int n_in,
                              void* d_out, int out_size) {
    const float* x = (const float*)d_in[0];
    const float* W = (const float*)d_in[1];
    const float* b = (const float*)d_in[2];
    float* out = (float*)d_out;

    cudaFuncSetAttribute(fused_kernel,
                         cudaFuncAttributeMaxDynamicSharedMemorySize, SMEM_BYTES);

    pad_kernel<<<(8 * 8 * PADC + 255) / 256, 256>>>(x);
    wfrag_kernel<<<(27 * 16 * 32 + 255) / 256, 256>>>(W);
    dim3 grid(1024, 2);
    fused_kernel<<<grid, 512, SMEM_BYTES>>>(b, out);
}